// round 13
// baseline (speedup 1.0000x reference)
#include <cuda_runtime.h>
#include <cuda_bf16.h>
#include <stdint.h>

// ---------------------------------------------------------------------------
// GLCM layer, one kernel, barrier-minimal:
//   out[b, a*64+code, py, px] =
//     (1/1024) * sum_{t in 36x36 ext. window} wy(i)*wx(j) *
//                [ code(reflect(t)) == code ]
// code(s) = 8*gl(s) + gl(clamp(s + shift_a)),  gl = ceil(x/32)-1.
//
// No SMEM staging: each position loads its 5 pixels straight from global
// (L2-resident input) and quantizes inline. Histograms are WARP-PRIVATE and
// zeroed by the owning warp, so the only CTA barrier is before the final
// reduce. Each CTA: one (batch, pool-cell, angle-group-of-4); angle groups
// own disjoint output channels. Interior cells (36/64) skip reflect/clamp.
// ---------------------------------------------------------------------------

#define H 256
#define W 256
#define NPIX (H * W)
#define NB 2
#define L2BINS 64
#define POOL 32
#define EXT 36              // 32 + 2*2 (box radius)
#define NT 512
#define NW 16               // one histogram copy per warp
#define NBINS 256           // 4 angles x 64 codes per CTA

// quantize: gl = ceil(v/32) - 1 == searchsorted_left(bins, v) - 1
__device__ __forceinline__ int quant(float v) {
    return __float2int_ru(v * 0.03125f) - 1;
}

// S = +1 for angle group 0 (angles 0-3, rows ty & ty-1),
// S = -1 for angle group 1 (angles 4-7, rows ty & ty+1).
// Bin order na,nb,nc,nd matches angle order within the group.
template<int S, bool INTERIOR>
__device__ __forceinline__
void hist_loop(const float* __restrict__ xb, int* __restrict__ whist,
               int tid, int Y0, int X0) {
    #pragma unroll
    for (int t = 0; t < 3; t++) {
        int pos = tid + t * NT;
        bool act = (t < 2) || (pos < EXT * EXT);
        int i = pos / EXT;
        int j = pos - i * EXT;

        int ty, tx, tyD, txA, txB;
        if (INTERIOR) {
            ty = Y0 - 2 + i;  tx = X0 - 2 + j;       // in [30,225]
            tyD = ty - S;  txA = tx + S;  txB = tx - S;
        } else {
            // reflect for the box-filter position, clamp for the shift
            ty = Y0 - 2 + i; if (ty < 0) ty = -ty; else if (ty > H - 1) ty = 2 * (H - 1) - ty;
            tx = X0 - 2 + j; if (tx < 0) tx = -tx; else if (tx > W - 1) tx = 2 * (W - 1) - tx;
            tyD = min(max(ty - S, 0), H - 1);
            txA = min(max(tx + S, 0), W - 1);
            txB = min(max(tx - S, 0), W - 1);
        }

        const float* r0 = xb + ty  * W;
        const float* r1 = xb + tyD * W;
        float v1 = 0.f, va = 0.f, vb = 0.f, vc = 0.f, vd = 0.f;
        if (act) {
            v1 = r0[tx];     // g1
            va = r0[txA];    // ( +S,  0)
            vb = r1[txA];    // ( +S, -S)
            vc = r1[tx];     // (  0, -S)
            vd = r1[txB];    // ( -S, -S)
        }

        // separable triangular weights 1,2,3,4,5,...,5,4,3,2,1
        int wgt = min(min(i + 1, EXT - i), 5) * min(min(j + 1, EXT - j), 5);

        if (act) {
            int c8 = quant(v1) << 3;
            int c0 = c8 + quant(va);
            int c1 = c8 + quant(vb);
            int c2 = c8 + quant(vc);
            int c3 = c8 + quant(vd);
            // guard matches reference one-hot: only codes in [0,64) counted
            if ((unsigned)c0 < (unsigned)L2BINS) atomicAdd(&whist[c0], wgt);
            if ((unsigned)c1 < (unsigned)L2BINS) atomicAdd(&whist[L2BINS + c1], wgt);
            if ((unsigned)c2 < (unsigned)L2BINS) atomicAdd(&whist[2 * L2BINS + c2], wgt);
            if ((unsigned)c3 < (unsigned)L2BINS) atomicAdd(&whist[3 * L2BINS + c3], wgt);
        }
    }
}

__global__ __launch_bounds__(NT, 2)
void glcm_kernel(const float* __restrict__ x, float* __restrict__ out) {
    const int px = blockIdx.x;            // 0..7
    const int py = blockIdx.y;            // 0..7
    const int b  = blockIdx.z >> 1;       // 0..1
    const int ag = blockIdx.z & 1;        // angle group
    const int X0 = px * POOL;
    const int Y0 = py * POOL;
    const int tid  = threadIdx.x;
    const int wid  = tid >> 5;
    const int lane = tid & 31;

    __shared__ int hist[NW][NBINS];       // 16 x 256 ints = 16 KB

    // each warp zeroes ITS OWN histogram -> no CTA barrier needed before atomics
    int* whist = hist[wid];
    ((int4*)whist)[lane]      = make_int4(0, 0, 0, 0);
    ((int4*)whist)[lane + 32] = make_int4(0, 0, 0, 0);
    __syncwarp();

    const float* xb = x + b * NPIX;
    const bool interior = ((unsigned)(px - 1) < 6u) && ((unsigned)(py - 1) < 6u);

    if (ag == 0) {
        if (interior) hist_loop< 1, true >(xb, whist, tid, Y0, X0);
        else          hist_loop< 1, false>(xb, whist, tid, Y0, X0);
    } else {
        if (interior) hist_loop<-1, true >(xb, whist, tid, Y0, X0);
        else          hist_loop<-1, false>(xb, whist, tid, Y0, X0);
    }
    __syncthreads();

    // reduce 16 warp histograms; write this CTA's disjoint output slice
    const float inv = 1.0f / (float)(POOL * POOL);
    if (tid < NBINS) {
        int s = 0;
        #pragma unroll
        for (int wp = 0; wp < NW; wp++) s += hist[wp][tid];
        int ch = ag * NBINS + tid;        // global channel in [0,512)
        out[((b * 512 + ch) * 8 + py) * 8 + px] = (float)s * inv;
    }
}

extern "C" void kernel_launch(void* const* d_in, const int* in_sizes, int n_in,
                              void* d_out, int out_size) {
    const float* x = (const float*)d_in[0];
    float* out = (float*)d_out;
    dim3 grid(8, 8, NB * 2);
    glcm_kernel<<<grid, NT>>>(x, out);
}